// round 9
// baseline (speedup 1.0000x reference)
#include <cuda_runtime.h>
#include <cuda_bf16.h>
#include <math.h>

// ---------------- problem constants ----------------
constexpr int NB = 4096;   // batch
constexpr int ND = 1024;   // model dim
constexpr int NT = 768;    // text dim
constexpr int NC = 16;     // classes
constexpr int NH = 4;      // heads
constexpr int NS = 4;      // sequence length of the stacked features
constexpr int HD = ND / NH; // 256

#define CURV 0.05f
#define SQC  0.22360679774997896f       // sqrt(0.05)
#define EPSF 1e-8f
#define ASINH_MAX 11.090354888959125f   // arcsinh(2^15)

// output layout (flattened tuple: logits, loss, oh, fh, oeu, feu)
constexpr long long LOSS_OFF = (long long)NB * NC;            // 65536
constexpr long long OH_OFF   = LOSS_OFF + 1;
constexpr long long FH_OFF   = OH_OFF  + (long long)NB * ND;
constexpr long long OEU_OFF  = FH_OFF  + (long long)NB * ND;
constexpr long long FEU_OFF  = OEU_OFF + (long long)NB * ND;

// ---------------- device scratch (no allocation allowed) ----------------
__device__ float g_gf0 [(size_t)NB * NS * ND];        // 64 MB  pre-attention features (residual)
__device__ float g_qkv [(size_t)NB * NS * 3 * ND];    // 192 MB qkv projection
__device__ float g_ctx [(size_t)NB * NS * ND];        // 64 MB  attention context
__device__ float g_attn[(size_t)NB * NS * ND];        // 64 MB  out-projection
__device__ float g_uo  [(size_t)NB * ND];             // 16 MB  order @ to_w^T + to_b
__device__ float g_uf  [(size_t)NB * ND];             // 16 MB  family @ tf_w^T + tf_b
__device__ float g_pen [2 * NB];                      // per-row penalties
__device__ float g_pp  [NC * ND];                     // p_expmap0(mlr_p)
__device__ float g_ap  [NC * ND];                     // mlr_a * conf
__device__ float g_cs  [4 * NC];                      // [x2 | a_norm | kk | pa]

// ---------------- helpers ----------------
__device__ __forceinline__ float blockReduceSum(float v, volatile float* sh) {
    int lane = threadIdx.x & 31, wid = threadIdx.x >> 5;
#pragma unroll
    for (int o = 16; o > 0; o >>= 1) v += __shfl_down_sync(0xffffffffu, v, o);
    if (lane == 0) sh[wid] = v;
    __syncthreads();
    if (wid == 0) {
        int nw = (blockDim.x + 31) >> 5;
        float t = (lane < nw) ? sh[lane] : 0.f;
#pragma unroll
        for (int o = 16; o > 0; o >>= 1) t += __shfl_down_sync(0xffffffffu, t, o);
        if (lane == 0) sh[32] = t;
    }
    __syncthreads();
    float r = sh[32];
    __syncthreads();
    return r;
}

// ---------------- 1) build gf0 = stack(p_logmap0(oh), p_logmap0(fh), oeu, feu) ----------------
__global__ void k_prep_gf(const float* __restrict__ ohy, const float* __restrict__ fhy,
                          const float* __restrict__ oeu, const float* __restrict__ feu) {
    int b = blockIdx.x, s = blockIdx.y;
    const float* src = (s == 0) ? ohy : (s == 1) ? fhy : (s == 2) ? oeu : feu;
    src += (size_t)b * ND;
    float* dst = g_gf0 + ((size_t)b * NS + s) * ND;
    __shared__ float sh[33];
    if (s < 2) {
        float acc = 0.f;
        for (int i = threadIdx.x; i < ND; i += blockDim.x) { float v = src[i]; acc += v * v; }
        float n2 = blockReduceSum(acc, sh);
        float n = fmaxf(sqrtf(n2), 1e-15f);
        float t = fminf(SQC * n, 1.f - 1e-5f);           // artanh arg clip (t >= 0)
        float art = 0.5f * (log1pf(t) - log1pf(-t));
        float f = art / (n * SQC);
        for (int i = threadIdx.x; i < ND; i += blockDim.x) dst[i] = src[i] * f;
    } else {
        for (int i = threadIdx.x; i < ND; i += blockDim.x) dst[i] = src[i];
    }
}

// ---------------- GEMM: Cout[M,N] = A[M,K] @ W[N,K]^T + bias[N] ----------------
#define BM 128
#define BN 128
#define BK 16
__global__ __launch_bounds__(256)
void k_gemm_bias(const float* __restrict__ A, const float* __restrict__ W,
                 const float* __restrict__ bias, float* __restrict__ Cout,
                 int M, int N, int K) {
    __shared__ float As[BK][BM + 4];
    __shared__ float Bs[BK][BN + 4];
    int bn = blockIdx.x, bm = blockIdx.y;
    int tid = threadIdx.x;
    int tx = tid & 15, ty = tid >> 4;

    const float* Ab = A + (size_t)bm * BM * K;
    const float* Wb = W + (size_t)bn * BN * K;

    float acc[8][8];
#pragma unroll
    for (int i = 0; i < 8; i++)
#pragma unroll
        for (int j = 0; j < 8; j++) acc[i][j] = 0.f;

    for (int kt = 0; kt < K; kt += BK) {
#pragma unroll
        for (int l = 0; l < 2; l++) {
            int slot = tid + l * 256;        // 0..511
            int row = slot >> 2;             // 0..127
            int cv  = slot & 3;              // float4 index within 16 cols
            float4 va = *(const float4*)(Ab + (size_t)row * K + kt + cv * 4);
            As[cv * 4 + 0][row] = va.x; As[cv * 4 + 1][row] = va.y;
            As[cv * 4 + 2][row] = va.z; As[cv * 4 + 3][row] = va.w;
            float4 vb = *(const float4*)(Wb + (size_t)row * K + kt + cv * 4);
            Bs[cv * 4 + 0][row] = vb.x; Bs[cv * 4 + 1][row] = vb.y;
            Bs[cv * 4 + 2][row] = vb.z; Bs[cv * 4 + 3][row] = vb.w;
        }
        __syncthreads();
#pragma unroll
        for (int k = 0; k < BK; k++) {
            float a[8], bvals[8];
            const float4* ap = (const float4*)&As[k][ty * 8];
            const float4* bp = (const float4*)&Bs[k][tx * 8];
            float4 a0 = ap[0], a1 = ap[1], b0 = bp[0], b1 = bp[1];
            a[0]=a0.x; a[1]=a0.y; a[2]=a0.z; a[3]=a0.w; a[4]=a1.x; a[5]=a1.y; a[6]=a1.z; a[7]=a1.w;
            bvals[0]=b0.x; bvals[1]=b0.y; bvals[2]=b0.z; bvals[3]=b0.w;
            bvals[4]=b1.x; bvals[5]=b1.y; bvals[6]=b1.z; bvals[7]=b1.w;
#pragma unroll
            for (int i = 0; i < 8; i++)
#pragma unroll
                for (int j = 0; j < 8; j++) acc[i][j] += a[i] * bvals[j];
        }
        __syncthreads();
    }

    int n0 = bn * BN + tx * 8;
#pragma unroll
    for (int i = 0; i < 8; i++) {
        int m = bm * BM + ty * 8 + i;
        float* cp = Cout + (size_t)m * N + n0;
#pragma unroll
        for (int j = 0; j < 8; j++) cp[j] = acc[i][j] + bias[n0 + j];
    }
}

// ---------------- 2) attention, S=4, one block per (b,h) ----------------
__global__ void k_attn() {
    int bh = blockIdx.x;
    int b = bh >> 2, h = bh & 3;
    __shared__ float q[NS][HD], kk[NS][HD], v[NS][HD];
    __shared__ float sc[NS][NS];
    int tid = threadIdx.x;
    const float* base = g_qkv + (size_t)b * NS * 3 * ND;
#pragma unroll
    for (int si = 0; si < NS; si++) {
        q [si][tid] = base[si * 3 * ND +          h * HD + tid];
        kk[si][tid] = base[si * 3 * ND + ND     + h * HD + tid];
        v [si][tid] = base[si * 3 * ND + 2 * ND + h * HD + tid];
    }
    __syncthreads();
    int w = tid >> 5, lane = tid & 31;
    for (int p = w; p < 16; p += 8) {
        int i = p >> 2, j = p & 3;
        float s = 0.f;
        for (int d = lane; d < HD; d += 32) s += q[i][d] * kk[j][d];
#pragma unroll
        for (int o = 16; o > 0; o >>= 1) s += __shfl_down_sync(0xffffffffu, s, o);
        if (lane == 0) sc[i][j] = s * 0.0625f;   // 1/sqrt(256)
    }
    __syncthreads();
    if (tid < 4) {
        float s0 = sc[tid][0], s1 = sc[tid][1], s2 = sc[tid][2], s3 = sc[tid][3];
        float m = fmaxf(fmaxf(s0, s1), fmaxf(s2, s3));
        float e0 = expf(s0 - m), e1 = expf(s1 - m), e2 = expf(s2 - m), e3 = expf(s3 - m);
        float inv = 1.f / (e0 + e1 + e2 + e3);
        sc[tid][0] = e0 * inv; sc[tid][1] = e1 * inv; sc[tid][2] = e2 * inv; sc[tid][3] = e3 * inv;
    }
    __syncthreads();
#pragma unroll
    for (int i = 0; i < NS; i++) {
        float o = sc[i][0] * v[0][tid] + sc[i][1] * v[1][tid] + sc[i][2] * v[2][tid] + sc[i][3] * v[3][tid];
        g_ctx[((size_t)b * NS + i) * ND + h * HD + tid] = o;
    }
}

// ---------------- 3) layernorm(gf0 + attn) + l_expmap0 for rows 0/1, write outputs ----------------
__global__ void k_ln_map(const float* __restrict__ ln_w, const float* __restrict__ ln_b,
                         float* __restrict__ dout) {
    int b = blockIdx.x, s = blockIdx.y;
    size_t off = ((size_t)b * NS + s) * ND;
    __shared__ float sh[33];
    int tid = threadIdx.x;
    float x[4];
    float sum = 0.f;
#pragma unroll
    for (int r = 0; r < 4; r++) {
        int i = tid + r * 256;
        x[r] = g_gf0[off + i] + g_attn[off + i];
        sum += x[r];
    }
    float mu = blockReduceSum(sum, sh) * (1.f / ND);
    float vs = 0.f;
#pragma unroll
    for (int r = 0; r < 4; r++) { float d = x[r] - mu; vs += d * d; }
    float var = blockReduceSum(vs, sh) * (1.f / ND);
    float rstd = rsqrtf(var + 1e-5f);
    float y[4];
#pragma unroll
    for (int r = 0; r < 4; r++) {
        int i = tid + r * 256;
        y[r] = (x[r] - mu) * rstd * ln_w[i] + ln_b[i];
    }
    long long base = (s == 0) ? OH_OFF : (s == 1) ? FH_OFF : (s == 2) ? OEU_OFF : FEU_OFF;
    float* dst = dout + base + (size_t)b * ND;
    if (s < 2) {
        float n2acc = 0.f;
#pragma unroll
        for (int r = 0; r < 4; r++) n2acc += y[r] * y[r];
        float n2 = blockReduceSum(n2acc, sh);
        float rc = SQC * sqrtf(n2);
        float si = fminf(fmaxf(rc, EPSF), ASINH_MAX);
        float f = sinhf(si) / fmaxf(rc, EPSF);
#pragma unroll
        for (int r = 0; r < 4; r++) dst[tid + r * 256] = y[r] * f;
    } else {
#pragma unroll
        for (int r = 0; r < 4; r++) dst[tid + r * 256] = y[r];
    }
}

// ---------------- 4) per-row entailment penalty ----------------
__global__ void k_pen(const float* __restrict__ dout) {
    int b = blockIdx.x, which = blockIdx.y;   // 0: order vs fh, 1: family vs oh
    const float* u = (which ? g_uf : g_uo) + (size_t)b * ND;
    const float* y = dout + (which ? OH_OFF : FH_OFF) + (size_t)b * ND;
    __shared__ float sh[33];
    int tid = threadIdx.x;
    float su2 = 0.f, suy = 0.f, sy2 = 0.f;
#pragma unroll
    for (int r = 0; r < 4; r++) {
        int i = tid + r * 256;
        float uu = u[i], yy = y[i];
        su2 += uu * uu; suy += uu * yy; sy2 += yy * yy;
    }
    su2 = blockReduceSum(su2, sh);
    suy = blockReduceSum(suy, sh);
    sy2 = blockReduceSum(sy2, sh);
    if (tid == 0) {
        float ru = sqrtf(su2);
        float rc = SQC * ru;
        float si = fminf(fmaxf(rc, EPSF), ASINH_MAX);
        float f = sinhf(si) / fmaxf(rc, EPSF);            // l_expmap0 scale
        float xx = f * f * su2;
        float xy = f * suy;
        float yy = sy2;
        float nx = f * ru;
        float xt = sqrtf(1.f / CURV + xx);
        float yt = sqrtf(1.f / CURV + yy);
        float cxy = CURV * (xy - xt * yt);
        float num = yt + cxy * xt;
        float den = sqrtf(fmaxf(cxy * cxy - 1.f, EPSF));
        float acos_in = num / (nx * den + EPSF);
        acos_in = fminf(fmaxf(acos_in, -1.f + EPSF), 1.f - EPSF);
        float angle = acosf(acos_in);
        float asin_in = 0.2f / (nx * SQC + EPSF);
        asin_in = fminf(fmaxf(asin_in, -1.f + EPSF), 1.f - EPSF);
        float ap = asinf(asin_in);
        g_pen[which * NB + b] = fmaxf(angle - ap, 0.f);
    }
}

// ---------------- 5) deterministic loss reduction ----------------
__global__ void k_loss(const int* __restrict__ mask, float* __restrict__ dout) {
    __shared__ float sh[33];
    int tid = threadIdx.x;
    float so = 0.f, sf = 0.f, cnt = 0.f;
    for (int i = tid; i < NB; i += blockDim.x) {
        so += g_pen[i];
        float m = (float)mask[i];
        sf += g_pen[NB + i] * m;
        cnt += m;
    }
    so = blockReduceSum(so, sh);
    sf = blockReduceSum(sf, sh);
    cnt = blockReduceSum(cnt, sh);
    if (tid == 0) {
        float ol = so * (1.f / NB);
        float fl = (cnt > 0.f) ? sf / fmaxf(cnt, 1.f) : 0.f;
        dout[LOSS_OFF] = ol + fl;
    }
}

// ---------------- 6) per-class MLR constants ----------------
__global__ void k_cls(const float* __restrict__ a, const float* __restrict__ p) {
    int c = blockIdx.x;
    const float* pr = p + (size_t)c * ND;
    const float* ar = a + (size_t)c * ND;
    __shared__ float sh[33];
    int tid = threadIdx.x;
    float sp2 = 0.f, sa2 = 0.f, spa = 0.f;
#pragma unroll
    for (int r = 0; r < 4; r++) {
        int i = tid + r * 256;
        float pv = pr[i], av = ar[i];
        sp2 += pv * pv; sa2 += av * av; spa += pv * av;
    }
    sp2 = blockReduceSum(sp2, sh);
    sa2 = blockReduceSum(sa2, sh);
    spa = blockReduceSum(spa, sh);
    float np = sqrtf(sp2);
    float n = fmaxf(np, 1e-15f);
    float f = tanhf(SQC * n) / (SQC * n);     // p_expmap0 scale
    float x2 = f * f * sp2;
    float conf = 1.f - CURV * x2;
    float anorm = fabsf(conf) * sqrtf(sa2);
    float kkv = (2.f / conf) * anorm / SQC;
    float pa = f * conf * spa;                // p_p . a_p
#pragma unroll
    for (int r = 0; r < 4; r++) {
        int i = tid + r * 256;
        g_pp[(size_t)c * ND + i] = f * pr[i];
        g_ap[(size_t)c * ND + i] = conf * ar[i];
    }
    if (tid == 0) {
        g_cs[c] = x2; g_cs[NC + c] = anorm; g_cs[2 * NC + c] = kkv; g_cs[3 * NC + c] = pa;
    }
}

// ---------------- 7) fused logmap0/expmap0/project + hyperbolic MLR logits ----------------
__global__ void k_logits(float* __restrict__ dout) {
    int b = blockIdx.x;
    const float* oh = dout + OH_OFF + (size_t)b * ND;
    __shared__ float sy[ND];
    __shared__ float sh[33];
    int tid = threadIdx.x;
    float acc = 0.f;
#pragma unroll
    for (int r = 0; r < 4; r++) {
        int i = tid + r * 256;
        float v = oh[i];
        sy[i] = v;
        acc += v * v;
    }
    float r2 = blockReduceSum(acc, sh);
    // hyp_pt = s * oh, with s a scalar function of ||oh||
    float rn = sqrtf(r2);
    float rc = SQC * rn;
    float g1 = asinhf(rc) / fmaxf(rc, EPSF);          // l_logmap0
    float nu = fmaxf(g1 * rn, 1e-15f);
    float f2 = tanhf(SQC * nu) / (SQC * nu);          // p_expmap0
    float nw = f2 * (g1 * rn);
    float maxn = (1.f - 0.004f) / SQC;
    float n3 = fmaxf(nw, 1e-15f);
    float scale = (n3 > maxn) ? (maxn / n3) : 1.f;    // p_project
    float s = g1 * f2 * scale;
    float y2 = s * s * r2;

    int w = tid >> 5, lane = tid & 31;
    for (int c = w; c < NC; c += 8) {
        const float* pp = g_pp + (size_t)c * ND;
        const float* ap = g_ap + (size_t)c * ND;
        float dp = 0.f, da = 0.f;
        for (int i = lane; i < ND; i += 32) {
            float v = sy[i];
            dp += v * pp[i];
            da += v * ap[i];
        }
#pragma unroll
        for (int o = 16; o > 0; o >>= 1) {
            dp += __shfl_down_sync(0xffffffffu, dp, o);
            da += __shfl_down_sync(0xffffffffu, da, o);
        }
        if (lane == 0) {
            float x2 = g_cs[c], anorm = g_cs[NC + c], kkv = g_cs[2 * NC + c], pa = g_cs[3 * NC + c];
            float xy = -s * dp;          // x = -p_p
            float ya = s * da;
            float A  = 1.f + 2.f * CURV * xy + CURV * y2;
            float Bc = 1.f - CURV * x2;
            float den0 = 1.f + 2.f * CURV * xy + CURV * CURV * x2 * y2 + 1e-5f;
            float mobdot = (A * (-pa) + Bc * ya) / den0;
            float num2 = 2.f * SQC * mobdot;
            float mob2 = (A * A * x2 + Bc * Bc * y2 + 2.f * A * Bc * xy) / (den0 * den0);
            float den2 = anorm * (1.f - CURV * mob2);
            dout[(size_t)b * NC + c] = kkv * asinhf(num2 / den2);
        }
    }
}

// ---------------- launch ----------------
extern "C" void kernel_launch(void* const* d_in, const int* in_sizes, int n_in,
                              void* d_out, int out_size) {
    const float* order_hyp  = (const float*)d_in[0];
    const float* family_hyp = (const float*)d_in[1];
    const float* order_euc  = (const float*)d_in[2];
    const float* family_euc = (const float*)d_in[3];
    const float* order      = (const float*)d_in[4];
    const float* family     = (const float*)d_in[5];
    const int*   mask       = (const int*)  d_in[6];
    const float* in_proj_w  = (const float*)d_in[7];
    const float* in_proj_b  = (const float*)d_in[8];
    const float* out_proj_w = (const float*)d_in[9];
    const float* out_proj_b = (const float*)d_in[10];
    const float* ln_w       = (const float*)d_in[11];
    const float* ln_b       = (const float*)d_in[12];
    const float* to_w       = (const float*)d_in[13];
    const float* to_b       = (const float*)d_in[14];
    const float* tf_w       = (const float*)d_in[15];
    const float* tf_b       = (const float*)d_in[16];
    const float* mlr_a      = (const float*)d_in[17];
    const float* mlr_p      = (const float*)d_in[18];
    float* out = (float*)d_out;

    float *p_gf0, *p_qkv, *p_ctx, *p_attn, *p_uo, *p_uf;
    cudaGetSymbolAddress((void**)&p_gf0,  g_gf0);
    cudaGetSymbolAddress((void**)&p_qkv,  g_qkv);
    cudaGetSymbolAddress((void**)&p_ctx,  g_ctx);
    cudaGetSymbolAddress((void**)&p_attn, g_attn);
    cudaGetSymbolAddress((void**)&p_uo,   g_uo);
    cudaGetSymbolAddress((void**)&p_uf,   g_uf);

    // 1) stacked features
    k_prep_gf<<<dim3(NB, NS), 256>>>(order_hyp, family_hyp, order_euc, family_euc);

    // 2) qkv = gf0 @ in_proj_w^T + in_proj_b   [16384,1024] x [3072,1024]^T
    k_gemm_bias<<<dim3(3 * ND / BN, NB * NS / BM), 256>>>(
        p_gf0, in_proj_w, in_proj_b, p_qkv, NB * NS, 3 * ND, ND);

    // 3) attention
    k_attn<<<NB * NH, HD>>>();

    // 4) out-proj: attn = ctx @ out_proj_w^T + out_proj_b
    k_gemm_bias<<<dim3(ND / BN, NB * NS / BM), 256>>>(
        p_ctx, out_proj_w, out_proj_b, p_attn, NB * NS, ND, ND);

    // 5) layernorm + l_expmap0, write oh/fh/oeu/feu to d_out
    k_ln_map<<<dim3(NB, NS), 256>>>(ln_w, ln_b, out);

    // 6) order/family text projections
    k_gemm_bias<<<dim3(ND / BN, NB / BM), 256>>>(order,  to_w, to_b, p_uo, NB, ND, NT);
    k_gemm_bias<<<dim3(ND / BN, NB / BM), 256>>>(family, tf_w, tf_b, p_uf, NB, ND, NT);

    // 7) penalties + loss
    k_pen<<<dim3(NB, 2), 256>>>(out);
    k_loss<<<1, 1024>>>(mask, out);

    // 8) MLR class constants + logits
    k_cls<<<NC, 256>>>(mlr_a, mlr_p);
    k_logits<<<NB, 256>>>(out);
}

// round 13
// speedup vs baseline: 2.4640x; 2.4640x over previous
#include <cuda_runtime.h>
#include <cuda_bf16.h>
#include <math.h>
#include <stdint.h>

// ---------------- problem constants ----------------
constexpr int NB = 4096;   // batch
constexpr int ND = 1024;   // model dim
constexpr int NT = 768;    // text dim
constexpr int NC = 16;     // classes
constexpr int NH = 4;      // heads
constexpr int NS = 4;      // sequence length of stacked features
constexpr int HD = ND / NH; // 256

#define CURV 0.05f
#define SQC  0.22360679774997896f       // sqrt(0.05)
#define EPSF 1e-8f
#define ASINH_MAX 11.090354888959125f   // arcsinh(2^15)

// output layout (flattened tuple: logits, loss, oh, fh, oeu, feu)
constexpr long long LOSS_OFF = (long long)NB * NC;
constexpr long long OH_OFF   = LOSS_OFF + 1;
constexpr long long FH_OFF   = OH_OFF  + (long long)NB * ND;
constexpr long long OEU_OFF  = FH_OFF  + (long long)NB * ND;
constexpr long long FEU_OFF  = OEU_OFF + (long long)NB * ND;

// ---------------- device scratch ----------------
__device__ float g_gf0 [(size_t)NB * NS * ND];
__device__ float g_qkv [(size_t)NB * NS * 3 * ND];
__device__ float g_ctx [(size_t)NB * NS * ND];
__device__ float g_attn[(size_t)NB * NS * ND];
__device__ float g_uo  [(size_t)NB * ND];
__device__ float g_uf  [(size_t)NB * ND];
__device__ float g_pen [2 * NB];
__device__ float g_pp  [NC * ND];
__device__ float g_ap  [NC * ND];
__device__ float g_cs  [4 * NC];

// split-bf16 staging: activations (reused: gf0_3 -> ctx3 -> order3+family3)
__device__ __nv_bfloat16 g_a3[(size_t)NB * NS * 3 * ND];
// weights, split-bf16
constexpr size_t W_IN3_OFF  = 0;                                      // 3072 x 3072
constexpr size_t W_OUT3_OFF = W_IN3_OFF  + (size_t)3 * ND * 3 * ND;   // 1024 x 3072
constexpr size_t W_TO3_OFF  = W_OUT3_OFF + (size_t)ND * 3 * ND;       // 1024 x 2304
constexpr size_t W_TF3_OFF  = W_TO3_OFF  + (size_t)ND * 3 * NT;
__device__ __nv_bfloat16 g_w3[W_TF3_OFF + (size_t)ND * 3 * NT];
constexpr size_t FAM3_OFF = (size_t)NB * 3 * NT;

// ---------------- small helpers ----------------
__device__ __forceinline__ float blockReduceSum(float v, volatile float* sh) {
    int lane = threadIdx.x & 31, wid = threadIdx.x >> 5;
#pragma unroll
    for (int o = 16; o > 0; o >>= 1) v += __shfl_down_sync(0xffffffffu, v, o);
    if (lane == 0) sh[wid] = v;
    __syncthreads();
    if (wid == 0) {
        int nw = (blockDim.x + 31) >> 5;
        float t = (lane < nw) ? sh[lane] : 0.f;
#pragma unroll
        for (int o = 16; o > 0; o >>= 1) t += __shfl_down_sync(0xffffffffu, t, o);
        if (lane == 0) sh[32] = t;
    }
    __syncthreads();
    float r = sh[32];
    __syncthreads();
    return r;
}

__device__ __forceinline__ uint32_t smem_u32(const void* p) {
    uint32_t a;
    asm("{ .reg .u64 t; cvta.to.shared.u64 t, %1; cvt.u32.u64 %0, t; }" : "=r"(a) : "l"(p));
    return a;
}

#define SWZ(o) ((o) ^ (((o) >> 3) & 0x70))

__device__ __forceinline__ void cp16(uint32_t dst, const void* src) {
    asm volatile("cp.async.cg.shared.global [%0], [%1], 16;" :: "r"(dst), "l"(src));
}
__device__ __forceinline__ void cp_commit() {
    asm volatile("cp.async.commit_group;" ::: "memory");
}
__device__ __forceinline__ void cp_wait1() {
    asm volatile("cp.async.wait_group 1;" ::: "memory");
}
__device__ __forceinline__ void ldm4(uint32_t* r, uint32_t a) {
    asm volatile("ldmatrix.sync.aligned.m8n8.x4.shared.b16 {%0,%1,%2,%3}, [%4];"
                 : "=r"(r[0]), "=r"(r[1]), "=r"(r[2]), "=r"(r[3]) : "r"(a));
}
__device__ __forceinline__ void mma16816(float* d, const uint32_t* a, uint32_t b0, uint32_t b1) {
    asm volatile(
        "mma.sync.aligned.m16n8k16.row.col.f32.bf16.bf16.f32 "
        "{%0,%1,%2,%3},{%4,%5,%6,%7},{%8,%9},{%0,%1,%2,%3};"
        : "+f"(d[0]), "+f"(d[1]), "+f"(d[2]), "+f"(d[3])
        : "r"(a[0]), "r"(a[1]), "r"(a[2]), "r"(a[3]), "r"(b0), "r"(b1));
}

// ---------------- mma.sync GEMM: C[M,N] = A[M,K3] @ B[N,K3]^T + bias ----------------
// 128x128 tile, BK=64 bf16 (128B rows, SW128 swizzle), 3-stage cp.async pipeline
constexpr uint32_t AB_STAGE  = 128 * 128;      // 16 KB per operand per stage
constexpr uint32_t STAGE_B   = 2 * AB_STAGE;   // 32 KB
constexpr int      STAGES    = 3;
constexpr uint32_t SMEM_GEMM = STAGES * STAGE_B;   // 96 KB

__device__ __forceinline__ void load_stage(uint32_t sb, int s,
                                           const __nv_bfloat16* Ab, const __nv_bfloat16* Bb,
                                           int K3, int kt, int tid) {
    uint32_t aS = sb + (uint32_t)s * STAGE_B;
    uint32_t bS = aS + AB_STAGE;
    const __nv_bfloat16* Ap = Ab + (size_t)kt * 64;
    const __nv_bfloat16* Bp = Bb + (size_t)kt * 64;
#pragma unroll
    for (int u = 0; u < 4; u++) {
        int id = tid + u * 256;
        int row = id >> 3, ch = id & 7;
        uint32_t o = SWZ((uint32_t)row * 128 + ch * 16);
        cp16(aS + o, Ap + (size_t)row * K3 + ch * 8);
        cp16(bS + o, Bp + (size_t)row * K3 + ch * 8);
    }
    cp_commit();
}

__global__ __launch_bounds__(256)
void k_gemm_mma(const __nv_bfloat16* __restrict__ A, const __nv_bfloat16* __restrict__ B,
                const float* __restrict__ bias, float* __restrict__ C,
                int M, int N, int K3) {
    extern __shared__ char smem[];
    uint32_t sb = smem_u32(smem);
    int tid = threadIdx.x, wid = tid >> 5, lane = tid & 31;
    int wm = wid >> 1, wn = wid & 1;           // 4x2 warp grid
    int lr = lane & 7, mi = lane >> 3;

    int bm = blockIdx.y * 128;
    int bn = blockIdx.x * 128;
    const __nv_bfloat16* Ab = A + (size_t)bm * K3;
    const __nv_bfloat16* Bb = B + (size_t)bn * K3;
    const int NK = K3 >> 6;

    // per-lane ldmatrix address precompute
    int aR = wm * 32 + lr + (mi & 1) * 8;      // + i*16 per m-atom
    uint32_t aKh = (uint32_t)(mi >> 1) * 16;
    uint32_t xa = (uint32_t)(aR & 7) * 16;
    uint32_t aOff0 = (uint32_t)aR * 128;
    uint32_t aOff1 = aOff0 + 16 * 128;
    int bR = wn * 64 + lr + (mi >> 1) * 8;     // + j2*16 per n-atom-pair
    uint32_t bKh = (uint32_t)(mi & 1) * 16;
    uint32_t xb = (uint32_t)(bR & 7) * 16;
    uint32_t bOff[4];
#pragma unroll
    for (int j2 = 0; j2 < 4; j2++) bOff[j2] = (uint32_t)(bR + j2 * 16) * 128;

    float acc[2][8][4];
#pragma unroll
    for (int i = 0; i < 2; i++)
#pragma unroll
        for (int j = 0; j < 8; j++)
#pragma unroll
            for (int r = 0; r < 4; r++) acc[i][j][r] = 0.f;

    load_stage(sb, 0, Ab, Bb, K3, 0, tid);
    load_stage(sb, 1, Ab, Bb, K3, 1, tid);

    for (int kt = 0; kt < NK; kt++) {
        cp_wait1();
        __syncthreads();
        int s = kt % STAGES;
        uint32_t aS = sb + (uint32_t)s * STAGE_B;
        uint32_t bS = aS + AB_STAGE;
#pragma unroll
        for (int ks = 0; ks < 4; ks++) {
            uint32_t kb = (uint32_t)ks * 32;
            uint32_t afrag[2][4];
            ldm4(afrag[0], aS + aOff0 + ((kb + aKh) ^ xa));
            ldm4(afrag[1], aS + aOff1 + ((kb + aKh) ^ xa));
            uint32_t bfrag[4][4];
#pragma unroll
            for (int j2 = 0; j2 < 4; j2++)
                ldm4(bfrag[j2], bS + bOff[j2] + ((kb + bKh) ^ xb));
#pragma unroll
            for (int i = 0; i < 2; i++)
#pragma unroll
                for (int j = 0; j < 8; j++)
                    mma16816(acc[i][j], afrag[i],
                             bfrag[j >> 1][(j & 1) * 2], bfrag[j >> 1][(j & 1) * 2 + 1]);
        }
        if (kt + 2 < NK) load_stage(sb, (kt + 2) % STAGES, Ab, Bb, K3, kt + 2, tid);
        else cp_commit();
    }

    // epilogue: direct float2 stores with bias
    int mBase = bm + wm * 32 + (lane >> 2);
    int nBase = bn + wn * 64 + 2 * (lane & 3);
#pragma unroll
    for (int i = 0; i < 2; i++) {
        int m0 = mBase + i * 16;
#pragma unroll
        for (int j = 0; j < 8; j++) {
            int n = nBase + j * 8;
            float bx = bias[n], by = bias[n + 1];
            float2 v0 = { acc[i][j][0] + bx, acc[i][j][1] + by };
            float2 v1 = { acc[i][j][2] + bx, acc[i][j][3] + by };
            *(float2*)(C + (size_t)m0 * N + n) = v0;
            *(float2*)(C + (size_t)(m0 + 8) * N + n) = v1;
        }
    }
}

// ---------------- split-bf16 converter ----------------
// weightMode=0 (activation): [hi | hi | lo];  weightMode=1 (weight): [hi | lo | hi]
__global__ void k_cvt3(const float* __restrict__ src, __nv_bfloat16* __restrict__ dst,
                       int K, int weightMode) {
    int r = blockIdx.y;
    int k = blockIdx.x * 256 + threadIdx.x;
    float x = src[(size_t)r * K + k];
    __nv_bfloat16 hi = __float2bfloat16(x);
    __nv_bfloat16 lo = __float2bfloat16(x - __bfloat162float(hi));
    size_t b3 = (size_t)r * 3 * K;
    dst[b3 + k] = hi;
    dst[b3 + K + k]     = weightMode ? lo : hi;
    dst[b3 + 2 * K + k] = weightMode ? hi : lo;
}

// ---------------- 1) gf0 = stack(p_logmap0(oh), p_logmap0(fh), oeu, feu) + split ----------------
__global__ void k_prep_gf(const float* __restrict__ ohy, const float* __restrict__ fhy,
                          const float* __restrict__ oeu, const float* __restrict__ feu) {
    int b = blockIdx.x, s = blockIdx.y;
    const float* src = (s == 0) ? ohy : (s == 1) ? fhy : (s == 2) ? oeu : feu;
    src += (size_t)b * ND;
    size_t row = (size_t)b * NS + s;
    float* dst = g_gf0 + row * ND;
    __nv_bfloat16* d3 = g_a3 + row * 3 * ND;
    __shared__ float sh[33];
    float f = 1.f;
    if (s < 2) {
        float acc = 0.f;
        for (int i = threadIdx.x; i < ND; i += blockDim.x) { float v = src[i]; acc += v * v; }
        float n2 = blockReduceSum(acc, sh);
        float n = fmaxf(sqrtf(n2), 1e-15f);
        float t = fminf(SQC * n, 1.f - 1e-5f);
        float art = 0.5f * (log1pf(t) - log1pf(-t));
        f = art / (n * SQC);
    }
    for (int i = threadIdx.x; i < ND; i += blockDim.x) {
        float v = src[i] * f;
        dst[i] = v;
        __nv_bfloat16 hi = __float2bfloat16(v);
        __nv_bfloat16 lo = __float2bfloat16(v - __bfloat162float(hi));
        d3[i] = hi; d3[ND + i] = hi; d3[2 * ND + i] = lo;
    }
}

// ---------------- 2) attention ----------------
__global__ void k_attn() {
    int bh = blockIdx.x;
    int b = bh >> 2, h = bh & 3;
    __shared__ float q[NS][HD], kk[NS][HD], v[NS][HD];
    __shared__ float sc[NS][NS];
    int tid = threadIdx.x;
    const float* base = g_qkv + (size_t)b * NS * 3 * ND;
#pragma unroll
    for (int si = 0; si < NS; si++) {
        q [si][tid] = base[si * 3 * ND +          h * HD + tid];
        kk[si][tid] = base[si * 3 * ND + ND     + h * HD + tid];
        v [si][tid] = base[si * 3 * ND + 2 * ND + h * HD + tid];
    }
    __syncthreads();
    int w = tid >> 5, lane = tid & 31;
    for (int p = w; p < 16; p += 8) {
        int i = p >> 2, j = p & 3;
        float s = 0.f;
        for (int d = lane; d < HD; d += 32) s += q[i][d] * kk[j][d];
#pragma unroll
        for (int o = 16; o > 0; o >>= 1) s += __shfl_down_sync(0xffffffffu, s, o);
        if (lane == 0) sc[i][j] = s * 0.0625f;
    }
    __syncthreads();
    if (tid < 4) {
        float s0 = sc[tid][0], s1 = sc[tid][1], s2 = sc[tid][2], s3 = sc[tid][3];
        float m = fmaxf(fmaxf(s0, s1), fmaxf(s2, s3));
        float e0 = expf(s0 - m), e1 = expf(s1 - m), e2 = expf(s2 - m), e3 = expf(s3 - m);
        float inv = 1.f / (e0 + e1 + e2 + e3);
        sc[tid][0] = e0 * inv; sc[tid][1] = e1 * inv; sc[tid][2] = e2 * inv; sc[tid][3] = e3 * inv;
    }
    __syncthreads();
#pragma unroll
    for (int i = 0; i < NS; i++) {
        float o = sc[i][0] * v[0][tid] + sc[i][1] * v[1][tid] + sc[i][2] * v[2][tid] + sc[i][3] * v[3][tid];
        g_ctx[((size_t)b * NS + i) * ND + h * HD + tid] = o;
    }
}

// ---------------- 3) layernorm + l_expmap0 ----------------
__global__ void k_ln_map(const float* __restrict__ ln_w, const float* __restrict__ ln_b,
                         float* __restrict__ dout) {
    int b = blockIdx.x, s = blockIdx.y;
    size_t off = ((size_t)b * NS + s) * ND;
    __shared__ float sh[33];
    int tid = threadIdx.x;
    float x[4];
    float sum = 0.f;
#pragma unroll
    for (int r = 0; r < 4; r++) {
        int i = tid + r * 256;
        x[r] = g_gf0[off + i] + g_attn[off + i];
        sum += x[r];
    }
    float mu = blockReduceSum(sum, sh) * (1.f / ND);
    float vs = 0.f;
#pragma unroll
    for (int r = 0; r < 4; r++) { float d = x[r] - mu; vs += d * d; }
    float var = blockReduceSum(vs, sh) * (1.f / ND);
    float rstd = rsqrtf(var + 1e-5f);
    float y[4];
#pragma unroll
    for (int r = 0; r < 4; r++) {
        int i = tid + r * 256;
        y[r] = (x[r] - mu) * rstd * ln_w[i] + ln_b[i];
    }
    long long base = (s == 0) ? OH_OFF : (s == 1) ? FH_OFF : (s == 2) ? OEU_OFF : FEU_OFF;
    float* dst = dout + base + (size_t)b * ND;
    if (s < 2) {
        float n2acc = 0.f;
#pragma unroll
        for (int r = 0; r < 4; r++) n2acc += y[r] * y[r];
        float n2 = blockReduceSum(n2acc, sh);
        float rc = SQC * sqrtf(n2);
        float si = fminf(fmaxf(rc, EPSF), ASINH_MAX);
        float f = sinhf(si) / fmaxf(rc, EPSF);
#pragma unroll
        for (int r = 0; r < 4; r++) dst[tid + r * 256] = y[r] * f;
    } else {
#pragma unroll
        for (int r = 0; r < 4; r++) dst[tid + r * 256] = y[r];
    }
}

// ---------------- 4) entailment penalties ----------------
__global__ void k_pen(const float* __restrict__ dout) {
    int b = blockIdx.x, which = blockIdx.y;
    const float* u = (which ? g_uf : g_uo) + (size_t)b * ND;
    const float* y = dout + (which ? OH_OFF : FH_OFF) + (size_t)b * ND;
    __shared__ float sh[33];
    int tid = threadIdx.x;
    float su2 = 0.f, suy = 0.f, sy2 = 0.f;
#pragma unroll
    for (int r = 0; r < 4; r++) {
        int i = tid + r * 256;
        float uu = u[i], yy = y[i];
        su2 += uu * uu; suy += uu * yy; sy2 += yy * yy;
    }
    su2 = blockReduceSum(su2, sh);
    suy = blockReduceSum(suy, sh);
    sy2 = blockReduceSum(sy2, sh);
    if (tid == 0) {
        float ru = sqrtf(su2);
        float rc = SQC * ru;
        float si = fminf(fmaxf(rc, EPSF), ASINH_MAX);
        float f = sinhf(si) / fmaxf(rc, EPSF);
        float xx = f * f * su2;
        float xy = f * suy;
        float yy = sy2;
        float nx = f * ru;
        float xt = sqrtf(1.f / CURV + xx);
        float yt = sqrtf(1.f / CURV + yy);
        float cxy = CURV * (xy - xt * yt);
        float num = yt + cxy * xt;
        float den = sqrtf(fmaxf(cxy * cxy - 1.f, EPSF));
        float acos_in = num / (nx * den + EPSF);
        acos_in = fminf(fmaxf(acos_in, -1.f + EPSF), 1.f - EPSF);
        float angle = acosf(acos_in);
        float asin_in = 0.2f / (nx * SQC + EPSF);
        asin_in = fminf(fmaxf(asin_in, -1.f + EPSF), 1.f - EPSF);
        float ap = asinf(asin_in);
        g_pen[which * NB + b] = fmaxf(angle - ap, 0.f);
    }
}

// ---------------- 5) loss reduction ----------------
__global__ void k_loss(const int* __restrict__ mask, float* __restrict__ dout) {
    __shared__ float sh[33];
    int tid = threadIdx.x;
    float so = 0.f, sf = 0.f, cnt = 0.f;
    for (int i = tid; i < NB; i += blockDim.x) {
        so += g_pen[i];
        float m = (float)mask[i];
        sf += g_pen[NB + i] * m;
        cnt += m;
    }
    so = blockReduceSum(so, sh);
    sf = blockReduceSum(sf, sh);
    cnt = blockReduceSum(cnt, sh);
    if (tid == 0) {
        float ol = so * (1.f / NB);
        float fl = (cnt > 0.f) ? sf / fmaxf(cnt, 1.f) : 0.f;
        dout[LOSS_OFF] = ol + fl;
    }
}

// ---------------- 6) per-class MLR constants ----------------
__global__ void k_cls(const float* __restrict__ a, const float* __restrict__ p) {
    int c = blockIdx.x;
    const float* pr = p + (size_t)c * ND;
    const float* ar = a + (size_t)c * ND;
    __shared__ float sh[33];
    int tid = threadIdx.x;
    float sp2 = 0.f, sa2 = 0.f, spa = 0.f;
#pragma unroll
    for (int r = 0; r < 4; r++) {
        int i = tid + r * 256;
        float pv = pr[i], av = ar[i];
        sp2 += pv * pv; sa2 += av * av; spa += pv * av;
    }
    sp2 = blockReduceSum(sp2, sh);
    sa2 = blockReduceSum(sa2, sh);
    spa = blockReduceSum(spa, sh);
    float np = sqrtf(sp2);
    float n = fmaxf(np, 1e-15f);
    float f = tanhf(SQC * n) / (SQC * n);
    float x2 = f * f * sp2;
    float conf = 1.f - CURV * x2;
    float anorm = fabsf(conf) * sqrtf(sa2);
    float kkv = (2.f / conf) * anorm / SQC;
    float pa = f * conf * spa;
#pragma unroll
    for (int r = 0; r < 4; r++) {
        int i = tid + r * 256;
        g_pp[(size_t)c * ND + i] = f * pr[i];
        g_ap[(size_t)c * ND + i] = conf * ar[i];
    }
    if (tid == 0) {
        g_cs[c] = x2; g_cs[NC + c] = anorm; g_cs[2 * NC + c] = kkv; g_cs[3 * NC + c] = pa;
    }
}

// ---------------- 7) fused maps + hyperbolic MLR logits ----------------
__global__ void k_logits(float* __restrict__ dout) {
    int b = blockIdx.x;
    const float* oh = dout + OH_OFF + (size_t)b * ND;
    __shared__ float sy[ND];
    __shared__ float sh[33];
    int tid = threadIdx.x;
    float acc = 0.f;
#pragma unroll
    for (int r = 0; r < 4; r++) {
        int i = tid + r * 256;
        float v = oh[i];
        sy[i] = v;
        acc += v * v;
    }
    float r2 = blockReduceSum(acc, sh);
    float rn = sqrtf(r2);
    float rc = SQC * rn;
    float g1 = asinhf(rc) / fmaxf(rc, EPSF);
    float nu = fmaxf(g1 * rn, 1e-15f);
    float f2 = tanhf(SQC * nu) / (SQC * nu);
    float nw = f2 * (g1 * rn);
    float maxn = (1.f - 0.004f) / SQC;
    float n3 = fmaxf(nw, 1e-15f);
    float scale = (n3 > maxn) ? (maxn / n3) : 1.f;
    float s = g1 * f2 * scale;
    float y2 = s * s * r2;

    int w = tid >> 5, lane = tid & 31;
    for (int c = w; c < NC; c += 8) {
        const float* pp = g_pp + (size_t)c * ND;
        const float* ap = g_ap + (size_t)c * ND;
        float dp = 0.f, da = 0.f;
        for (int i = lane; i < ND; i += 32) {
            float v = sy[i];
            dp += v * pp[i];
            da += v * ap[i];
        }
#pragma unroll
        for (int o = 16; o > 0; o >>= 1) {
            dp += __shfl_down_sync(0xffffffffu, dp, o);
            da += __shfl_down_sync(0xffffffffu, da, o);
        }
        if (lane == 0) {
            float x2 = g_cs[c], anorm = g_cs[NC + c], kkv = g_cs[2 * NC + c], pa = g_cs[3 * NC + c];
            float xy = -s * dp;
            float ya = s * da;
            float A  = 1.f + 2.f * CURV * xy + CURV * y2;
            float Bc = 1.f - CURV * x2;
            float den0 = 1.f + 2.f * CURV * xy + CURV * CURV * x2 * y2 + 1e-5f;
            float mobdot = (A * (-pa) + Bc * ya) / den0;
            float num2 = 2.f * SQC * mobdot;
            float mob2 = (A * A * x2 + Bc * Bc * y2 + 2.f * A * Bc * xy) / (den0 * den0);
            float den2 = anorm * (1.f - CURV * mob2);
            dout[(size_t)b * NC + c] = kkv * asinhf(num2 / den2);
        }
    }
}

// ---------------- launch ----------------
extern "C" void kernel_launch(void* const* d_in, const int* in_sizes, int n_in,
                              void* d_out, int out_size) {
    const float* order_hyp  = (const float*)d_in[0];
    const float* family_hyp = (const float*)d_in[1];
    const float* order_euc  = (const float*)d_in[2];
    const float* family_euc = (const float*)d_in[3];
    const float* order      = (const float*)d_in[4];
    const float* family     = (const float*)d_in[5];
    const int*   mask       = (const int*)  d_in[6];
    const float* in_proj_w  = (const float*)d_in[7];
    const float* in_proj_b  = (const float*)d_in[8];
    const float* out_proj_w = (const float*)d_in[9];
    const float* out_proj_b = (const float*)d_in[10];
    const float* ln_w       = (const float*)d_in[11];
    const float* ln_b       = (const float*)d_in[12];
    const float* to_w       = (const float*)d_in[13];
    const float* to_b       = (const float*)d_in[14];
    const float* tf_w       = (const float*)d_in[15];
    const float* tf_b       = (const float*)d_in[16];
    const float* mlr_a      = (const float*)d_in[17];
    const float* mlr_p      = (const float*)d_in[18];
    float* out = (float*)d_out;

    float *p_qkv, *p_ctx, *p_attn, *p_uo, *p_uf;
    __nv_bfloat16 *p_a3, *p_w3;
    cudaGetSymbolAddress((void**)&p_qkv,  g_qkv);
    cudaGetSymbolAddress((void**)&p_ctx,  g_ctx);
    cudaGetSymbolAddress((void**)&p_attn, g_attn);
    cudaGetSymbolAddress((void**)&p_uo,   g_uo);
    cudaGetSymbolAddress((void**)&p_uf,   g_uf);
    cudaGetSymbolAddress((void**)&p_a3,   g_a3);
    cudaGetSymbolAddress((void**)&p_w3,   g_w3);

    cudaFuncSetAttribute(k_gemm_mma, cudaFuncAttributeMaxDynamicSharedMemorySize, SMEM_GEMM);

    // weight splits (hi | lo | hi)
    k_cvt3<<<dim3(ND / 256, 3 * ND), 256>>>(in_proj_w,  p_w3 + W_IN3_OFF,  ND, 1);
    k_cvt3<<<dim3(ND / 256, ND),     256>>>(out_proj_w, p_w3 + W_OUT3_OFF, ND, 1);
    k_cvt3<<<dim3(NT / 256, ND),     256>>>(to_w,       p_w3 + W_TO3_OFF,  NT, 1);
    k_cvt3<<<dim3(NT / 256, ND),     256>>>(tf_w,       p_w3 + W_TF3_OFF,  NT, 1);

    // 1) stacked features (fp32 residual + split-bf16 activation)
    k_prep_gf<<<dim3(NB, NS), 256>>>(order_hyp, family_hyp, order_euc, family_euc);

    // 2) QKV: [16384,3072] = gf0_3[16384,3072] @ w_in3[3072,3072]^T + bias
    k_gemm_mma<<<dim3(3 * ND / 128, NB * NS / 128), 256, SMEM_GEMM>>>(
        p_a3, p_w3 + W_IN3_OFF, in_proj_b, p_qkv, NB * NS, 3 * ND, 3 * ND);

    // 3) attention
    k_attn<<<NB * NH, HD>>>();

    // 4) ctx split, then out-proj
    k_cvt3<<<dim3(ND / 256, NB * NS), 256>>>(p_ctx, p_a3, ND, 0);
    k_gemm_mma<<<dim3(ND / 128, NB * NS / 128), 256, SMEM_GEMM>>>(
        p_a3, p_w3 + W_OUT3_OFF, out_proj_b, p_attn, NB * NS, ND, 3 * ND);

    // 5) layernorm + l_expmap0 -> d_out
    k_ln_map<<<dim3(NB, NS), 256>>>(ln_w, ln_b, out);

    // 6) text projections
    k_cvt3<<<dim3(NT / 256, NB), 256>>>(order,  p_a3, NT, 0);
    k_cvt3<<<dim3(NT / 256, NB), 256>>>(family, p_a3 + FAM3_OFF, NT, 0);
    k_gemm_mma<<<dim3(ND / 128, NB / 128), 256, SMEM_GEMM>>>(
        p_a3, p_w3 + W_TO3_OFF, to_b, p_uo, NB, ND, 3 * NT);
    k_gemm_mma<<<dim3(ND / 128, NB / 128), 256, SMEM_GEMM>>>(
        p_a3 + FAM3_OFF, p_w3 + W_TF3_OFF, tf_b, p_uf, NB, ND, 3 * NT);

    // 7) penalties + loss
    k_pen<<<dim3(NB, 2), 256>>>(out);
    k_loss<<<1, 1024>>>(mask, out);

    // 8) MLR constants + logits
    k_cls<<<NC, 256>>>(mlr_a, mlr_p);
    k_logits<<<NB, 256>>>(out);
}